// round 7
// baseline (speedup 1.0000x reference)
#include <cuda_runtime.h>
#include <cuda_bf16.h>
#include <math.h>
#include <stdint.h>

#define NROWS 500000
#define DIN   256
#define DHID  128
#define NHEAD 4
#define HBLK  32
#define DOUT  4
#define TM    128

// smem offsets from 1024-aligned base
#define OFF_IDX 0        // 128 int
#define OFF_W2  512      // 128 float (W2 * 1/sqrt(128))
#define OFF_B   1024     // 512 cat-rows x 32 bf16 (64 B/row) = 32 KB
#define OFF_A   33792    // 128 rows x 128 cat-cols bf16 (256 B/row) = 32 KB
#define SMEM_REQ (33792 + 32768 + 1024)

// ---------------- scratch ----------------
__device__ int g_cnt[NHEAD];
__device__ int g_idx[NHEAD][NROWS];

// ---------------- kernel 1: zero counters ----------------
__global__ void zero_kernel() {
    if (threadIdx.x < NHEAD) g_cnt[threadIdx.x] = 0;
}

// ---------------- kernel 2: bucket rows by head ----------------
__global__ void scatter_kernel(const int* __restrict__ heads, int n) {
    __shared__ int s_cnt[NHEAD];
    __shared__ int s_base[NHEAD];
    int t = blockIdx.x * blockDim.x + threadIdx.x;
    if (threadIdx.x < NHEAD) s_cnt[threadIdx.x] = 0;
    __syncthreads();
    int h = 0, rank = 0;
    bool valid = (t < n);
    if (valid) {
        h = heads[t];
        rank = atomicAdd(&s_cnt[h], 1);
    }
    __syncthreads();
    if (threadIdx.x < NHEAD)
        s_base[threadIdx.x] = atomicAdd(&g_cnt[threadIdx.x], s_cnt[threadIdx.x]);
    __syncthreads();
    if (valid) g_idx[h][s_base[h] + rank] = t;
}

// ---------------- PTX helpers (base ISA only: sm_75/80+) ----------------
__device__ __forceinline__ uint32_t smem_u32(const void* p) {
    uint32_t a;
    asm("{ .reg .u64 t; cvta.to.shared.u64 t, %1; cvt.u32.u64 %0, t; }"
        : "=r"(a) : "l"(p));
    return a;
}
__device__ __forceinline__ void ldm_x4(uint32_t* r, uint32_t addr) {
    asm volatile("ldmatrix.sync.aligned.m8n8.x4.shared.b16 {%0,%1,%2,%3}, [%4];"
                 : "=r"(r[0]), "=r"(r[1]), "=r"(r[2]), "=r"(r[3]) : "r"(addr));
}
__device__ __forceinline__ void ldm_x4_t(uint32_t* r, uint32_t addr) {
    asm volatile("ldmatrix.sync.aligned.m8n8.x4.trans.shared.b16 {%0,%1,%2,%3}, [%4];"
                 : "=r"(r[0]), "=r"(r[1]), "=r"(r[2]), "=r"(r[3]) : "r"(addr));
}
__device__ __forceinline__ void mma_bf16(float* d, const uint32_t* a, const uint32_t* b) {
    asm volatile("mma.sync.aligned.m16n8k16.row.col.f32.bf16.bf16.f32 "
                 "{%0,%1,%2,%3}, {%4,%5,%6,%7}, {%8,%9}, {%0,%1,%2,%3};"
                 : "+f"(d[0]), "+f"(d[1]), "+f"(d[2]), "+f"(d[3])
                 : "r"(a[0]), "r"(a[1]), "r"(a[2]), "r"(a[3]), "r"(b[0]), "r"(b[1]));
}
// split f into bf16 hi/lo, packed word = {lo:hi} (hi in low half = mem-first)
__device__ __forceinline__ uint32_t splitpack(float f) {
    __nv_bfloat16 hb = __float2bfloat16(f);
    float hf = __bfloat162float(hb);
    __nv_bfloat16 lb = __float2bfloat16(f - hf);
    return (uint32_t)__bfloat16_as_ushort(hb) |
           ((uint32_t)__bfloat16_as_ushort(lb) << 16);
}

// ---------------- kernel 3: bucketed fused GEMM on HMMA ----------------
__global__ void __launch_bounds__(128)
mma_kernel(const float* __restrict__ x,
           const float* __restrict__ W1,
           const float* __restrict__ W2,
           float* __restrict__ out) {
    extern __shared__ char smraw[];

    // ---- resolve (head, tile) ----
    const int c0 = g_cnt[0], c1 = g_cnt[1], c2 = g_cnt[2], c3 = g_cnt[3];
    const int t0 = (c0 + TM - 1) >> 7, t1 = (c1 + TM - 1) >> 7,
              t2 = (c2 + TM - 1) >> 7, t3 = (c3 + TM - 1) >> 7;
    int b = blockIdx.x;
    int hd, cnt;
    if (b < t0)              { hd = 0; cnt = c0; }
    else if ((b -= t0) < t1) { hd = 1; cnt = c1; }
    else if ((b -= t1) < t2) { hd = 2; cnt = c2; }
    else if ((b -= t2) < t3) { hd = 3; cnt = c3; }
    else return;
    const int start = b << 7;

    const int tid  = threadIdx.x;
    const int lane = tid & 31;
    const int warp = tid >> 5;

    const uint32_t raw  = smem_u32(smraw);
    const uint32_t base = (raw + 1023u) & ~1023u;
    char* smc = smraw + (base - raw);

    // ---- prologue: row indices, scaled W2, B tile (W1 hi/lo interleaved) ----
    {
        int rr = start + tid;
        if (rr >= cnt) rr = cnt - 1;
        *(int*)(smc + OFF_IDX + tid * 4) = g_idx[hd][rr];
    }
    {
        int j = tid >> 2, d = tid & 3;
        *(float*)(smc + OFF_W2 + tid * 4) =
            W2[(hd * HBLK + j) * DOUT + d] * 0.08838834764831845f;
    }
    {
        // thread: n = tid&31 (col), k0 = tid>>5; 64 orig-k each
        const int n  = tid & 31;
        const int k0 = tid >> 5;
        const uint32_t nc = (uint32_t)(n >> 3);
        const float* wp = W1 + hd * HBLK + n;
        #pragma unroll 4
        for (int i = 0; i < 64; ++i) {
            int k = k0 + 4 * i;
            float w = wp[k * DHID] * 0.0625f;       // fold 1/sqrt(256)
            __nv_bfloat16 hb = __float2bfloat16(w);
            float hf = __bfloat162float(hb);
            __nv_bfloat16 lb = __float2bfloat16(w - hf);
            // cat rows 2k (hi), 2k+1 (lo); swizzle chunk = nc ^ ((row>>1)&3) = nc^(k&3)
            uint32_t off = OFF_B + (uint32_t)(2 * k) * 64u +
                           (((uint32_t)nc ^ (uint32_t)(k & 3)) << 4) +
                           (uint32_t)(n & 7) * 2u;
            *(__nv_bfloat16*)(smc + off)      = hb;
            *(__nv_bfloat16*)(smc + off + 64) = lb;
        }
    }
    __syncthreads();

    // ---- per-lane constants ----
    // gather: half sh = lane>>4, 16B-chunk s = lane&15; row = i*8 + warp*2 + sh
    const int sh = lane >> 4;
    const int s  = lane & 15;
    const int rlow = warp * 2 + sh;            // row & 7 (constant)
    // mma addressing
    const int g     = lane >> 3;               // ldmatrix lane group
    const int l7    = lane & 7;
    const int ghalf = g >> 1;                  // A: k-chunk half / B: n-chunk half
    const int arow  = warp * 32 + (g & 1) * 8 + l7;      // + mt*16
    const uint32_t abase = base + OFF_A + (uint32_t)arow * 256u;
    const int klo   = (g & 1) * 8 + l7;        // B k within 16-step

    float acc[2][4][4];
    #pragma unroll
    for (int mt = 0; mt < 2; ++mt)
        #pragma unroll
        for (int nt = 0; nt < 4; ++nt)
            #pragma unroll
            for (int j = 0; j < 4; ++j) acc[mt][nt][j] = 0.f;

    #pragma unroll 1
    for (int ch = 0; ch < 4; ++ch) {
        // ---- gather + split-convert 128 rows x 64 orig-k into A tile ----
        const char* xb = (const char*)x + (uint32_t)(ch * 256 + s * 16);
        #pragma unroll 4
        for (int i = 0; i < 16; ++i) {
            int r = i * 8 + rlow;
            uint32_t ridx = *(const uint32_t*)(smc + OFF_IDX + r * 4);
            float4 v = *(const float4*)(xb + (size_t)ridx * 1024u);
            uint4 wv;
            wv.x = splitpack(v.x);
            wv.y = splitpack(v.y);
            wv.z = splitpack(v.z);
            wv.w = splitpack(v.w);
            *(uint4*)(smc + OFF_A + (uint32_t)r * 256u +
                      ((uint32_t)(s ^ rlow) << 4)) = wv;
        }
        __syncthreads();

        // ---- MMA: 8 k-steps x 2 exact-split passes ----
        #pragma unroll
        for (int ks = 0; ks < 8; ++ks) {
            uint32_t afr[2][4];
            #pragma unroll
            for (int mt = 0; mt < 2; ++mt) {
                uint32_t cc = (uint32_t)(2 * ks + ghalf);
                ldm_x4(afr[mt], abase + (uint32_t)mt * 4096u +
                                ((cc ^ (uint32_t)l7) << 4));
            }
            #pragma unroll
            for (int var = 0; var < 2; ++var) {
                int row = (ch * 128 + ks * 16 + klo) ^ var;   // var1: pair-swapped rows
                uint32_t bsw = (uint32_t)((row >> 1) & 3);
                #pragma unroll
                for (int np = 0; np < 2; ++np) {
                    uint32_t nc2 = (uint32_t)(np * 2 + ghalf);
                    uint32_t bfr[4];
                    ldm_x4_t(bfr, base + OFF_B + (uint32_t)row * 64u +
                                  ((nc2 ^ bsw) << 4));
                    #pragma unroll
                    for (int mt = 0; mt < 2; ++mt) {
                        mma_bf16(acc[mt][np * 2 + 0], afr[mt], bfr + 0);
                        mma_bf16(acc[mt][np * 2 + 1], afr[mt], bfr + 2);
                    }
                }
            }
        }
        __syncthreads();
    }

    // ---- epilogue: silu + W2, quad reduction, scattered store ----
    const int q  = lane & 3;
    const int r0 = lane >> 2;
    float4 wc[4][2];
    #pragma unroll
    for (int nt = 0; nt < 4; ++nt)
        #pragma unroll
        for (int j = 0; j < 2; ++j)
            wc[nt][j] = *(const float4*)(smc + OFF_W2 + (nt * 8 + q * 2 + j) * 16);

    float4 osum[2][2];
    #pragma unroll
    for (int mt = 0; mt < 2; ++mt)
        #pragma unroll
        for (int hh = 0; hh < 2; ++hh)
            osum[mt][hh] = make_float4(0.f, 0.f, 0.f, 0.f);

    #pragma unroll
    for (int mt = 0; mt < 2; ++mt)
        #pragma unroll
        for (int nt = 0; nt < 4; ++nt)
            #pragma unroll
            for (int idx = 0; idx < 4; ++idx) {
                int hh = idx >> 1, j = idx & 1;
                float hv = acc[mt][nt][idx];
                float sv = hv / (1.f + __expf(-hv));
                osum[mt][hh].x += sv * wc[nt][j].x;
                osum[mt][hh].y += sv * wc[nt][j].y;
                osum[mt][hh].z += sv * wc[nt][j].z;
                osum[mt][hh].w += sv * wc[nt][j].w;
            }

    #pragma unroll
    for (int mbit = 1; mbit <= 2; mbit <<= 1)
        #pragma unroll
        for (int mt = 0; mt < 2; ++mt)
            #pragma unroll
            for (int hh = 0; hh < 2; ++hh) {
                osum[mt][hh].x += __shfl_xor_sync(0xffffffffu, osum[mt][hh].x, mbit);
                osum[mt][hh].y += __shfl_xor_sync(0xffffffffu, osum[mt][hh].y, mbit);
                osum[mt][hh].z += __shfl_xor_sync(0xffffffffu, osum[mt][hh].z, mbit);
                osum[mt][hh].w += __shfl_xor_sync(0xffffffffu, osum[mt][hh].w, mbit);
            }

    if (q == 0) {
        #pragma unroll
        for (int mt = 0; mt < 2; ++mt)
            #pragma unroll
            for (int hh = 0; hh < 2; ++hh) {
                int rl = warp * 32 + mt * 16 + hh * 8 + r0;
                if (start + rl < cnt) {
                    int ridx = *(const int*)(smc + OFF_IDX + rl * 4);
                    *(float4*)(out + (size_t)ridx * DOUT) = osum[mt][hh];
                }
            }
    }
}

// ---------------- launch ----------------
extern "C" void kernel_launch(void* const* d_in, const int* in_sizes, int n_in,
                              void* d_out, int out_size) {
    const float* x     = (const float*)d_in[0];
    const float* W1    = (const float*)d_in[1];
    const float* W2    = (const float*)d_in[2];
    const int*   heads = (const int*)d_in[3];
    int n = in_sizes[3];

    static int attr_done = 0;
    if (!attr_done) {
        cudaFuncSetAttribute(mma_kernel,
                             cudaFuncAttributeMaxDynamicSharedMemorySize, SMEM_REQ);
        attr_done = 1;
    }

    zero_kernel<<<1, 32>>>();
    scatter_kernel<<<(n + 255) / 256, 256>>>(heads, n);

    int nt = (n + TM - 1) / TM + (NHEAD - 1);
    mma_kernel<<<nt, 128, SMEM_REQ>>>(x, W1, W2, (float*)d_out);
}

// round 8
// speedup vs baseline: 2.1925x; 2.1925x over previous
#include <cuda_runtime.h>
#include <cuda_bf16.h>
#include <math.h>
#include <stdint.h>

#define NROWS 500000
#define DIN   256
#define DHID  128
#define NHEAD 4
#define HBLK  32
#define DOUT  4
#define TM    128

// smem offsets from 1024-aligned base
#define OFF_IDX 0        // 128 int
#define OFF_W2  512      // 128 float (W2 * 1/sqrt(128))
#define OFF_B   1024     // 512 cat-rows x 32 bf16 (64 B/row) = 32 KB
#define OFF_A   33792    // 128 rows x 128 cat-cols bf16 (256 B/row) = 32 KB
#define SMEM_REQ (33792 + 32768 + 1024)

// ---------------- scratch ----------------
__device__ int g_cnt[NHEAD];
__device__ int g_idx[NHEAD][NROWS];

// ---------------- kernel 1: zero counters ----------------
__global__ void zero_kernel() {
    if (threadIdx.x < NHEAD) g_cnt[threadIdx.x] = 0;
}

// ---------------- kernel 2: bucket rows by head ----------------
__global__ void scatter_kernel(const int* __restrict__ heads, int n) {
    __shared__ int s_cnt[NHEAD];
    __shared__ int s_base[NHEAD];
    int t = blockIdx.x * blockDim.x + threadIdx.x;
    if (threadIdx.x < NHEAD) s_cnt[threadIdx.x] = 0;
    __syncthreads();
    int h = 0, rank = 0;
    bool valid = (t < n);
    if (valid) {
        h = heads[t];
        rank = atomicAdd(&s_cnt[h], 1);
    }
    __syncthreads();
    if (threadIdx.x < NHEAD)
        s_base[threadIdx.x] = atomicAdd(&g_cnt[threadIdx.x], s_cnt[threadIdx.x]);
    __syncthreads();
    if (valid) g_idx[h][s_base[h] + rank] = t;
}

// ---------------- PTX helpers (base ISA: sm_75/80+) ----------------
__device__ __forceinline__ uint32_t smem_u32(const void* p) {
    uint32_t a;
    asm("{ .reg .u64 t; cvta.to.shared.u64 t, %1; cvt.u32.u64 %0, t; }"
        : "=r"(a) : "l"(p));
    return a;
}
__device__ __forceinline__ void ldm_x4(uint32_t* r, uint32_t addr) {
    asm volatile("ldmatrix.sync.aligned.m8n8.x4.shared.b16 {%0,%1,%2,%3}, [%4];"
                 : "=r"(r[0]), "=r"(r[1]), "=r"(r[2]), "=r"(r[3]) : "r"(addr));
}
__device__ __forceinline__ void ldm_x4_t(uint32_t* r, uint32_t addr) {
    asm volatile("ldmatrix.sync.aligned.m8n8.x4.trans.shared.b16 {%0,%1,%2,%3}, [%4];"
                 : "=r"(r[0]), "=r"(r[1]), "=r"(r[2]), "=r"(r[3]) : "r"(addr));
}
__device__ __forceinline__ void mma_bf16(float* d, const uint32_t* a, const uint32_t* b) {
    asm volatile("mma.sync.aligned.m16n8k16.row.col.f32.bf16.bf16.f32 "
                 "{%0,%1,%2,%3}, {%4,%5,%6,%7}, {%8,%9}, {%0,%1,%2,%3};"
                 : "+f"(d[0]), "+f"(d[1]), "+f"(d[2]), "+f"(d[3])
                 : "r"(a[0]), "r"(a[1]), "r"(a[2]), "r"(a[3]), "r"(b[0]), "r"(b[1]));
}
// split 2 floats to bf16 hi/lo; w0 = {lo0:hi0}, w1 = {lo1:hi1} (hi in low half)
__device__ __forceinline__ void splitpack2(float f0, float f1,
                                           uint32_t& w0, uint32_t& w1) {
    uint32_t h, l;
    asm("cvt.rn.bf16x2.f32 %0, %1, %2;" : "=r"(h) : "f"(f1), "f"(f0));
    float f0h = __uint_as_float(h << 16);
    float f1h = __uint_as_float(h & 0xffff0000u);
    asm("cvt.rn.bf16x2.f32 %0, %1, %2;" : "=r"(l) : "f"(f1 - f1h), "f"(f0 - f0h));
    asm("prmt.b32 %0, %1, %2, 0x5410;" : "=r"(w0) : "r"(h), "r"(l));
    asm("prmt.b32 %0, %1, %2, 0x7632;" : "=r"(w1) : "r"(h), "r"(l));
}

// ---------------- kernel 3: bucketed fused GEMM on HMMA ----------------
__global__ void __launch_bounds__(128, 3)
mma_kernel(const float* __restrict__ x,
           const float* __restrict__ W1,
           const float* __restrict__ W2,
           float* __restrict__ out) {
    extern __shared__ char smraw[];

    // ---- resolve (head, tile) ----
    const int c0 = g_cnt[0], c1 = g_cnt[1], c2 = g_cnt[2], c3 = g_cnt[3];
    const int t0 = (c0 + TM - 1) >> 7, t1 = (c1 + TM - 1) >> 7,
              t2 = (c2 + TM - 1) >> 7, t3 = (c3 + TM - 1) >> 7;
    int b = blockIdx.x;
    int hd, cnt;
    if (b < t0)              { hd = 0; cnt = c0; }
    else if ((b -= t0) < t1) { hd = 1; cnt = c1; }
    else if ((b -= t1) < t2) { hd = 2; cnt = c2; }
    else if ((b -= t2) < t3) { hd = 3; cnt = c3; }
    else return;
    const int start = b << 7;

    const int tid  = threadIdx.x;
    const int lane = tid & 31;
    const int warp = tid >> 5;

    const uint32_t raw  = smem_u32(smraw);
    const uint32_t base = (raw + 1023u) & ~1023u;
    char* smc = smraw + (base - raw);

    // ---- prologue: row indices, scaled W2, B tile (W1 hi/lo interleaved) ----
    {
        int rr = start + tid;
        if (rr >= cnt) rr = cnt - 1;
        *(int*)(smc + OFF_IDX + tid * 4) = g_idx[hd][rr];
    }
    {
        int j = tid >> 2, d = tid & 3;
        *(float*)(smc + OFF_W2 + tid * 4) =
            W2[(hd * HBLK + j) * DOUT + d] * 0.08838834764831845f;
    }
    {
        const int n  = tid & 31;
        const int k0 = tid >> 5;
        const uint32_t nc = (uint32_t)(n >> 3);
        const float* wp = W1 + hd * HBLK + n;
        #pragma unroll 4
        for (int i = 0; i < 64; ++i) {
            int k = k0 + 4 * i;
            float w = wp[k * DHID] * 0.0625f;       // fold 1/sqrt(256)
            __nv_bfloat16 hb = __float2bfloat16(w);
            float hf = __bfloat162float(hb);
            __nv_bfloat16 lb = __float2bfloat16(w - hf);
            uint32_t off = OFF_B + (uint32_t)(2 * k) * 64u +
                           (((uint32_t)nc ^ (uint32_t)(k & 3)) << 4) +
                           (uint32_t)(n & 7) * 2u;
            *(__nv_bfloat16*)(smc + off)      = hb;
            *(__nv_bfloat16*)(smc + off + 64) = lb;
        }
    }
    __syncthreads();

    // ---- per-lane constants ----
    const int sh   = lane >> 4;
    const int s    = lane & 15;
    const int rlow = warp * 2 + sh;            // row & 7 (constant)
    const int g    = lane >> 3;
    const int l7   = lane & 7;
    const int ghalf = g >> 1;
    const int arow  = warp * 32 + (g & 1) * 8 + l7;
    const uint32_t abase = base + OFF_A + (uint32_t)arow * 256u;
    const int klo   = (g & 1) * 8 + l7;

    // ---- precompute gather byte-offsets (once) ----
    uint32_t rofs[16];
    #pragma unroll
    for (int i = 0; i < 16; ++i)
        rofs[i] = *(const uint32_t*)(smc + OFF_IDX + (i * 8 + rlow) * 4) * 1024u
                  + (uint32_t)(s * 16);
    const uint32_t sts_sw = ((uint32_t)(s ^ rlow)) << 4;
    const char* xB = (const char*)x;

    float acc[2][4][4];
    #pragma unroll
    for (int mt = 0; mt < 2; ++mt)
        #pragma unroll
        for (int nt = 0; nt < 4; ++nt)
            #pragma unroll
            for (int j = 0; j < 4; ++j) acc[mt][nt][j] = 0.f;

    // prologue: stage chunk0 group0
    float4 st[4];
    #pragma unroll
    for (int j = 0; j < 4; ++j) st[j] = *(const float4*)(xB + rofs[j]);

    #pragma unroll 1
    for (int ch = 0; ch < 4; ++ch) {
        // ---- pipelined gather: prefetch next group, convert+STS current ----
        #pragma unroll
        for (int gg = 0; gg < 4; ++gg) {
            float4 nx[4];
            int      ni   = (gg + 1) * 4;
            uint32_t nadd = (uint32_t)(ch * 256);
            if (gg == 3) { ni = 0; nadd += 256; }
            bool have_next = !(ch == 3 && gg == 3);
            #pragma unroll
            for (int j = 0; j < 4; ++j)
                if (have_next) nx[j] = *(const float4*)(xB + rofs[ni + j] + nadd);
            #pragma unroll
            for (int j = 0; j < 4; ++j) {
                int r = (gg * 4 + j) * 8 + rlow;
                uint4 wv;
                splitpack2(st[j].x, st[j].y, wv.x, wv.y);
                splitpack2(st[j].z, st[j].w, wv.z, wv.w);
                *(uint4*)(smc + OFF_A + (uint32_t)r * 256u + sts_sw) = wv;
            }
            #pragma unroll
            for (int j = 0; j < 4; ++j) st[j] = nx[j];
        }
        __syncthreads();

        // ---- MMA: 8 k-steps x 2 exact-split passes ----
        #pragma unroll
        for (int ks = 0; ks < 8; ++ks) {
            uint32_t afr[2][4];
            #pragma unroll
            for (int mt = 0; mt < 2; ++mt) {
                uint32_t cc = (uint32_t)(2 * ks + ghalf);
                ldm_x4(afr[mt], abase + (uint32_t)mt * 4096u +
                                ((cc ^ (uint32_t)l7) << 4));
            }
            #pragma unroll
            for (int var = 0; var < 2; ++var) {
                int row = (ch * 128 + ks * 16 + klo) ^ var;
                uint32_t bsw = (uint32_t)((row >> 1) & 3);
                #pragma unroll
                for (int np = 0; np < 2; ++np) {
                    uint32_t nc2 = (uint32_t)(np * 2 + ghalf);
                    uint32_t bfr[4];
                    ldm_x4_t(bfr, base + OFF_B + (uint32_t)row * 64u +
                                  ((nc2 ^ bsw) << 4));
                    #pragma unroll
                    for (int mt = 0; mt < 2; ++mt) {
                        mma_bf16(acc[mt][np * 2 + 0], afr[mt], bfr + 0);
                        mma_bf16(acc[mt][np * 2 + 1], afr[mt], bfr + 2);
                    }
                }
            }
        }
        __syncthreads();
    }

    // ---- epilogue: silu + W2, quad reduction, scattered store ----
    const int q  = lane & 3;
    const int r0 = lane >> 2;

    float4 osum[2][2];
    #pragma unroll
    for (int mt = 0; mt < 2; ++mt)
        #pragma unroll
        for (int hh = 0; hh < 2; ++hh)
            osum[mt][hh] = make_float4(0.f, 0.f, 0.f, 0.f);

    #pragma unroll
    for (int nt = 0; nt < 4; ++nt) {
        float4 wcj[2];
        #pragma unroll
        for (int j = 0; j < 2; ++j)
            wcj[j] = *(const float4*)(smc + OFF_W2 + (nt * 8 + q * 2 + j) * 16);
        #pragma unroll
        for (int mt = 0; mt < 2; ++mt)
            #pragma unroll
            for (int idx = 0; idx < 4; ++idx) {
                int hh = idx >> 1, j = idx & 1;
                float hv = acc[mt][nt][idx];
                float sv = hv / (1.f + __expf(-hv));
                osum[mt][hh].x += sv * wcj[j].x;
                osum[mt][hh].y += sv * wcj[j].y;
                osum[mt][hh].z += sv * wcj[j].z;
                osum[mt][hh].w += sv * wcj[j].w;
            }
    }

    #pragma unroll
    for (int mbit = 1; mbit <= 2; mbit <<= 1)
        #pragma unroll
        for (int mt = 0; mt < 2; ++mt)
            #pragma unroll
            for (int hh = 0; hh < 2; ++hh) {
                osum[mt][hh].x += __shfl_xor_sync(0xffffffffu, osum[mt][hh].x, mbit);
                osum[mt][hh].y += __shfl_xor_sync(0xffffffffu, osum[mt][hh].y, mbit);
                osum[mt][hh].z += __shfl_xor_sync(0xffffffffu, osum[mt][hh].z, mbit);
                osum[mt][hh].w += __shfl_xor_sync(0xffffffffu, osum[mt][hh].w, mbit);
            }

    if (q == 0) {
        #pragma unroll
        for (int mt = 0; mt < 2; ++mt)
            #pragma unroll
            for (int hh = 0; hh < 2; ++hh) {
                int rl = warp * 32 + mt * 16 + hh * 8 + r0;
                if (start + rl < cnt) {
                    int ridx = *(const int*)(smc + OFF_IDX + rl * 4);
                    *(float4*)(out + (size_t)ridx * DOUT) = osum[mt][hh];
                }
            }
    }
}

// ---------------- launch ----------------
extern "C" void kernel_launch(void* const* d_in, const int* in_sizes, int n_in,
                              void* d_out, int out_size) {
    const float* x     = (const float*)d_in[0];
    const float* W1    = (const float*)d_in[1];
    const float* W2    = (const float*)d_in[2];
    const int*   heads = (const int*)d_in[3];
    int n = in_sizes[3];

    static int attr_done = 0;
    if (!attr_done) {
        cudaFuncSetAttribute(mma_kernel,
                             cudaFuncAttributeMaxDynamicSharedMemorySize, SMEM_REQ);
        attr_done = 1;
    }

    zero_kernel<<<1, 32>>>();
    scatter_kernel<<<(n + 255) / 256, 256>>>(heads, n);

    int nt = (n + TM - 1) / TM + (NHEAD - 1);
    mma_kernel<<<nt, 128, SMEM_REQ>>>(x, W1, W2, (float*)d_out);
}

// round 9
// speedup vs baseline: 2.2602x; 1.0309x over previous
#include <cuda_runtime.h>
#include <cuda_bf16.h>
#include <math.h>
#include <stdint.h>

#define NROWS 500000
#define DIN   256
#define DHID  128
#define NHEAD 4
#define HBLK  32
#define DOUT  4
#define TM    128

// smem offsets from 1024-aligned base
#define OFF_IDX 0        // 128 int
#define OFF_W2  512      // 128 float (W2 * 1/sqrt(128))
#define OFF_B   1024     // 512 cat-rows x 32 bf16 (64 B/row) = 32 KB
#define OFF_A   33792    // 128 rows x 128 cat-cols bf16 (256 B/row) = 32 KB
#define SMEM_REQ (33792 + 32768 + 1024)

// ---------------- scratch ----------------
__device__ int g_cnt[NHEAD];
__device__ unsigned int g_done;          // monotonically increasing ticket
__device__ int g_idx[NHEAD][NROWS];

// ---------------- kernel 1: bucket rows by head ----------------
__global__ void scatter_kernel(const int* __restrict__ heads, int n) {
    __shared__ int s_cnt[NHEAD];
    __shared__ int s_base[NHEAD];
    int t = blockIdx.x * blockDim.x + threadIdx.x;
    if (threadIdx.x < NHEAD) s_cnt[threadIdx.x] = 0;
    __syncthreads();
    int h = 0, rank = 0;
    bool valid = (t < n);
    if (valid) {
        h = heads[t];
        rank = atomicAdd(&s_cnt[h], 1);
    }
    __syncthreads();
    if (threadIdx.x < NHEAD)
        s_base[threadIdx.x] = atomicAdd(&g_cnt[threadIdx.x], s_cnt[threadIdx.x]);
    __syncthreads();
    if (valid) g_idx[h][s_base[h] + rank] = t;
}

// ---------------- PTX helpers (base ISA: sm_75/80+) ----------------
__device__ __forceinline__ uint32_t smem_u32(const void* p) {
    uint32_t a;
    asm("{ .reg .u64 t; cvta.to.shared.u64 t, %1; cvt.u32.u64 %0, t; }"
        : "=r"(a) : "l"(p));
    return a;
}
__device__ __forceinline__ void ldm_x4(uint32_t* r, uint32_t addr) {
    asm volatile("ldmatrix.sync.aligned.m8n8.x4.shared.b16 {%0,%1,%2,%3}, [%4];"
                 : "=r"(r[0]), "=r"(r[1]), "=r"(r[2]), "=r"(r[3]) : "r"(addr));
}
__device__ __forceinline__ void ldm_x4_t(uint32_t* r, uint32_t addr) {
    asm volatile("ldmatrix.sync.aligned.m8n8.x4.trans.shared.b16 {%0,%1,%2,%3}, [%4];"
                 : "=r"(r[0]), "=r"(r[1]), "=r"(r[2]), "=r"(r[3]) : "r"(addr));
}
__device__ __forceinline__ void mma_bf16(float* d, const uint32_t* a, const uint32_t* b) {
    asm volatile("mma.sync.aligned.m16n8k16.row.col.f32.bf16.bf16.f32 "
                 "{%0,%1,%2,%3}, {%4,%5,%6,%7}, {%8,%9}, {%0,%1,%2,%3};"
                 : "+f"(d[0]), "+f"(d[1]), "+f"(d[2]), "+f"(d[3])
                 : "r"(a[0]), "r"(a[1]), "r"(a[2]), "r"(a[3]), "r"(b[0]), "r"(b[1]));
}
__device__ __forceinline__ uint32_t hswap(uint32_t v) {
    uint32_t r;
    asm("prmt.b32 %0, %1, %1, 0x1032;" : "=r"(r) : "r"(v));
    return r;
}
// split 2 floats to bf16 hi/lo; w0 = {lo0:hi0}, w1 = {lo1:hi1} (hi in low half)
__device__ __forceinline__ void splitpack2(float f0, float f1,
                                           uint32_t& w0, uint32_t& w1) {
    uint32_t h, l;
    asm("cvt.rn.bf16x2.f32 %0, %1, %2;" : "=r"(h) : "f"(f1), "f"(f0));
    float f0h = __uint_as_float(h << 16);
    float f1h = __uint_as_float(h & 0xffff0000u);
    asm("cvt.rn.bf16x2.f32 %0, %1, %2;" : "=r"(l) : "f"(f1 - f1h), "f"(f0 - f0h));
    asm("prmt.b32 %0, %1, %2, 0x5410;" : "=r"(w0) : "r"(h), "r"(l));
    asm("prmt.b32 %0, %1, %2, 0x7632;" : "=r"(w1) : "r"(h), "r"(l));
}

// ---------------- kernel 2: bucketed fused GEMM on HMMA ----------------
__global__ void __launch_bounds__(128, 3)
mma_kernel(const float* __restrict__ x,
           const float* __restrict__ W1,
           const float* __restrict__ W2,
           float* __restrict__ out) {
    extern __shared__ char smraw[];
    __shared__ int s_c[NHEAD];

    const int tid  = threadIdx.x;
    const int lane = tid & 31;
    const int warp = tid >> 5;

    // ---- read counts once (thread 0), publish via smem, then ticket ----
    if (tid == 0) {
        s_c[0] = g_cnt[0]; s_c[1] = g_cnt[1];
        s_c[2] = g_cnt[2]; s_c[3] = g_cnt[3];
    }
    __syncthreads();           // all CTA threads see s_c; g_cnt reads complete
    if (tid == 0) {
        unsigned int old = atomicAdd(&g_done, 1u);
        if (old % gridDim.x == gridDim.x - 1) {      // last CTA of this launch
            g_cnt[0] = 0; g_cnt[1] = 0; g_cnt[2] = 0; g_cnt[3] = 0;
        }
    }

    // ---- resolve (head, tile) ----
    const int c0 = s_c[0], c1 = s_c[1], c2 = s_c[2], c3 = s_c[3];
    const int t0 = (c0 + TM - 1) >> 7, t1 = (c1 + TM - 1) >> 7,
              t2 = (c2 + TM - 1) >> 7, t3 = (c3 + TM - 1) >> 7;
    int b = blockIdx.x;
    int hd, cnt;
    if (b < t0)              { hd = 0; cnt = c0; }
    else if ((b -= t0) < t1) { hd = 1; cnt = c1; }
    else if ((b -= t1) < t2) { hd = 2; cnt = c2; }
    else if ((b -= t2) < t3) { hd = 3; cnt = c3; }
    else return;
    const int start = b << 7;

    const uint32_t raw  = smem_u32(smraw);
    const uint32_t base = (raw + 1023u) & ~1023u;
    char* smc = smraw + (base - raw);

    // ---- prologue: row indices, scaled W2, B tile (W1 hi/lo interleaved) ----
    {
        int rr = start + tid;
        if (rr >= cnt) rr = cnt - 1;
        *(int*)(smc + OFF_IDX + tid * 4) = g_idx[hd][rr];
    }
    {
        int j = tid >> 2, d = tid & 3;
        *(float*)(smc + OFF_W2 + tid * 4) =
            W2[(hd * HBLK + j) * DOUT + d] * 0.08838834764831845f;
    }
    {
        const int n  = tid & 31;
        const int k0 = tid >> 5;
        const uint32_t nc = (uint32_t)(n >> 3);
        const float* wp = W1 + hd * HBLK + n;
        #pragma unroll 4
        for (int i = 0; i < 64; ++i) {
            int k = k0 + 4 * i;
            float w = wp[k * DHID] * 0.0625f;       // fold 1/sqrt(256)
            __nv_bfloat16 hb = __float2bfloat16(w);
            float hf = __bfloat162float(hb);
            __nv_bfloat16 lb = __float2bfloat16(w - hf);
            uint32_t off = OFF_B + (uint32_t)(2 * k) * 64u +
                           (((uint32_t)nc ^ (uint32_t)(k & 3)) << 4) +
                           (uint32_t)(n & 7) * 2u;
            *(__nv_bfloat16*)(smc + off)      = hb;
            *(__nv_bfloat16*)(smc + off + 64) = lb;
        }
    }
    __syncthreads();

    // ---- per-lane constants ----
    const int sh   = lane >> 4;
    const int s    = lane & 15;
    const int rlow = warp * 2 + sh;            // row & 7 (constant)
    const int g    = lane >> 3;
    const int l7   = lane & 7;
    const int ghalf = g >> 1;
    const int arow  = warp * 32 + (g & 1) * 8 + l7;
    const uint32_t abase = base + OFF_A + (uint32_t)arow * 256u;
    const int klo   = (g & 1) * 8 + l7;

    // ---- precompute gather byte-offsets (once) ----
    uint32_t rofs[16];
    #pragma unroll
    for (int i = 0; i < 16; ++i)
        rofs[i] = *(const uint32_t*)(smc + OFF_IDX + (i * 8 + rlow) * 4) * 1024u
                  + (uint32_t)(s * 16);
    const uint32_t sts_sw = ((uint32_t)(s ^ rlow)) << 4;
    const char* xB = (const char*)x;

    float acc[2][4][4];
    #pragma unroll
    for (int mt = 0; mt < 2; ++mt)
        #pragma unroll
        for (int nt = 0; nt < 4; ++nt)
            #pragma unroll
            for (int j = 0; j < 4; ++j) acc[mt][nt][j] = 0.f;

    // prologue: stage chunk0 group0
    float4 st[4];
    #pragma unroll
    for (int j = 0; j < 4; ++j) st[j] = *(const float4*)(xB + rofs[j]);

    #pragma unroll 1
    for (int ch = 0; ch < 4; ++ch) {
        // ---- pipelined gather: prefetch next group, convert+STS current ----
        #pragma unroll
        for (int gg = 0; gg < 4; ++gg) {
            float4 nx[4];
            int      ni   = (gg + 1) * 4;
            uint32_t nadd = (uint32_t)(ch * 256);
            if (gg == 3) { ni = 0; nadd += 256; }
            bool have_next = !(ch == 3 && gg == 3);
            #pragma unroll
            for (int j = 0; j < 4; ++j)
                if (have_next) nx[j] = *(const float4*)(xB + rofs[ni + j] + nadd);
            #pragma unroll
            for (int j = 0; j < 4; ++j) {
                int r = (gg * 4 + j) * 8 + rlow;
                uint4 wv;
                splitpack2(st[j].x, st[j].y, wv.x, wv.y);
                splitpack2(st[j].z, st[j].w, wv.z, wv.w);
                *(uint4*)(smc + OFF_A + (uint32_t)r * 256u + sts_sw) = wv;
            }
            #pragma unroll
            for (int j = 0; j < 4; ++j) st[j] = nx[j];
        }
        __syncthreads();

        // ---- MMA: 8 k-steps; pass 2 via halfword-swapped A (no extra LDSM) ----
        #pragma unroll
        for (int ks = 0; ks < 8; ++ks) {
            uint32_t afr[2][4], asw[2][4], bfr[2][4];
            #pragma unroll
            for (int mt = 0; mt < 2; ++mt) {
                uint32_t cc = (uint32_t)(2 * ks + ghalf);
                ldm_x4(afr[mt], abase + (uint32_t)mt * 4096u +
                                ((cc ^ (uint32_t)l7) << 4));
            }
            {
                int row = ch * 128 + ks * 16 + klo;
                uint32_t bsw = (uint32_t)((row >> 1) & 3);
                #pragma unroll
                for (int np = 0; np < 2; ++np) {
                    uint32_t nc2 = (uint32_t)(np * 2 + ghalf);
                    ldm_x4_t(bfr[np], base + OFF_B + (uint32_t)row * 64u +
                                      ((nc2 ^ bsw) << 4));
                }
            }
            #pragma unroll
            for (int mt = 0; mt < 2; ++mt)
                #pragma unroll
                for (int j = 0; j < 4; ++j) asw[mt][j] = hswap(afr[mt][j]);
            #pragma unroll
            for (int mt = 0; mt < 2; ++mt)
                #pragma unroll
                for (int np = 0; np < 2; ++np) {
                    mma_bf16(acc[mt][np * 2 + 0], afr[mt], bfr[np] + 0);
                    mma_bf16(acc[mt][np * 2 + 1], afr[mt], bfr[np] + 2);
                    mma_bf16(acc[mt][np * 2 + 0], asw[mt], bfr[np] + 0);
                    mma_bf16(acc[mt][np * 2 + 1], asw[mt], bfr[np] + 2);
                }
        }
        __syncthreads();
    }

    // ---- epilogue: silu + W2, quad reduction, scattered store ----
    const int q  = lane & 3;
    const int r0 = lane >> 2;

    float4 osum[2][2];
    #pragma unroll
    for (int mt = 0; mt < 2; ++mt)
        #pragma unroll
        for (int hh = 0; hh < 2; ++hh)
            osum[mt][hh] = make_float4(0.f, 0.f, 0.f, 0.f);

    #pragma unroll
    for (int nt = 0; nt < 4; ++nt) {
        float4 wcj[2];
        #pragma unroll
        for (int j = 0; j < 2; ++j)
            wcj[j] = *(const float4*)(smc + OFF_W2 + (nt * 8 + q * 2 + j) * 16);
        #pragma unroll
        for (int mt = 0; mt < 2; ++mt)
            #pragma unroll
            for (int idx = 0; idx < 4; ++idx) {
                int hh = idx >> 1, j = idx & 1;
                float hv = acc[mt][nt][idx];
                float sv = hv / (1.f + __expf(-hv));
                osum[mt][hh].x += sv * wcj[j].x;
                osum[mt][hh].y += sv * wcj[j].y;
                osum[mt][hh].z += sv * wcj[j].z;
                osum[mt][hh].w += sv * wcj[j].w;
            }
    }

    #pragma unroll
    for (int mbit = 1; mbit <= 2; mbit <<= 1)
        #pragma unroll
        for (int mt = 0; mt < 2; ++mt)
            #pragma unroll
            for (int hh = 0; hh < 2; ++hh) {
                osum[mt][hh].x += __shfl_xor_sync(0xffffffffu, osum[mt][hh].x, mbit);
                osum[mt][hh].y += __shfl_xor_sync(0xffffffffu, osum[mt][hh].y, mbit);
                osum[mt][hh].z += __shfl_xor_sync(0xffffffffu, osum[mt][hh].z, mbit);
                osum[mt][hh].w += __shfl_xor_sync(0xffffffffu, osum[mt][hh].w, mbit);
            }

    if (q == 0) {
        #pragma unroll
        for (int mt = 0; mt < 2; ++mt)
            #pragma unroll
            for (int hh = 0; hh < 2; ++hh) {
                int rl = warp * 32 + mt * 16 + hh * 8 + r0;
                if (start + rl < cnt) {
                    int ridx = *(const int*)(smc + OFF_IDX + rl * 4);
                    *(float4*)(out + (size_t)ridx * DOUT) = osum[mt][hh];
                }
            }
    }
}

// ---------------- launch ----------------
extern "C" void kernel_launch(void* const* d_in, const int* in_sizes, int n_in,
                              void* d_out, int out_size) {
    const float* x     = (const float*)d_in[0];
    const float* W1    = (const float*)d_in[1];
    const float* W2    = (const float*)d_in[2];
    const int*   heads = (const int*)d_in[3];
    int n = in_sizes[3];

    static int attr_done = 0;
    if (!attr_done) {
        cudaFuncSetAttribute(mma_kernel,
                             cudaFuncAttributeMaxDynamicSharedMemorySize, SMEM_REQ);
        attr_done = 1;
    }

    scatter_kernel<<<(n + 255) / 256, 256>>>(heads, n);

    int nt = (n + TM - 1) / TM + (NHEAD - 1);
    mma_kernel<<<nt, 128, SMEM_REQ>>>(x, W1, W2, (float*)d_out);
}

// round 10
// speedup vs baseline: 2.4003x; 1.0620x over previous
#include <cuda_runtime.h>
#include <cuda_bf16.h>
#include <math.h>
#include <stdint.h>

#define NROWS 500000
#define DIN   256
#define DHID  128
#define NHEAD 4
#define HBLK  32
#define DOUT  4
#define TM    128
#define NCHUNK 16            // 16 orig-k per chunk

// smem offsets from 1024-aligned base
#define OFF_IDX 0            // 128 int
#define OFF_W2  512          // 128 float
#define OFF_B   1024         // 512 cat-rows x 32 bf16 (64 B/row) = 32 KB
#define OFF_A0  33792        // A buf 0: 128 rows x 64 B = 8 KB
#define OFF_A1  41984        // A buf 1: 8 KB
#define SMEM_REQ (50176 + 1024)

// ---------------- scratch ----------------
__device__ int g_cnt[NHEAD];
__device__ unsigned int g_done;
__device__ int g_idx[NHEAD][NROWS];

// ---------------- kernel 1: bucket rows by head ----------------
__global__ void scatter_kernel(const int* __restrict__ heads, int n) {
    __shared__ int s_cnt[NHEAD];
    __shared__ int s_base[NHEAD];
    int t = blockIdx.x * blockDim.x + threadIdx.x;
    if (threadIdx.x < NHEAD) s_cnt[threadIdx.x] = 0;
    __syncthreads();
    int h = 0, rank = 0;
    bool valid = (t < n);
    if (valid) {
        h = heads[t];
        rank = atomicAdd(&s_cnt[h], 1);
    }
    __syncthreads();
    if (threadIdx.x < NHEAD)
        s_base[threadIdx.x] = atomicAdd(&g_cnt[threadIdx.x], s_cnt[threadIdx.x]);
    __syncthreads();
    if (valid) g_idx[h][s_base[h] + rank] = t;
}

// ---------------- PTX helpers ----------------
__device__ __forceinline__ uint32_t smem_u32(const void* p) {
    uint32_t a;
    asm("{ .reg .u64 t; cvta.to.shared.u64 t, %1; cvt.u32.u64 %0, t; }"
        : "=r"(a) : "l"(p));
    return a;
}
__device__ __forceinline__ void ldm_x4(uint32_t* r, uint32_t addr) {
    asm volatile("ldmatrix.sync.aligned.m8n8.x4.shared.b16 {%0,%1,%2,%3}, [%4];"
                 : "=r"(r[0]), "=r"(r[1]), "=r"(r[2]), "=r"(r[3]) : "r"(addr));
}
__device__ __forceinline__ void ldm_x4_t(uint32_t* r, uint32_t addr) {
    asm volatile("ldmatrix.sync.aligned.m8n8.x4.trans.shared.b16 {%0,%1,%2,%3}, [%4];"
                 : "=r"(r[0]), "=r"(r[1]), "=r"(r[2]), "=r"(r[3]) : "r"(addr));
}
__device__ __forceinline__ void mma_bf16(float* d, const uint32_t* a, const uint32_t* b) {
    asm volatile("mma.sync.aligned.m16n8k16.row.col.f32.bf16.bf16.f32 "
                 "{%0,%1,%2,%3}, {%4,%5,%6,%7}, {%8,%9}, {%0,%1,%2,%3};"
                 : "+f"(d[0]), "+f"(d[1]), "+f"(d[2]), "+f"(d[3])
                 : "r"(a[0]), "r"(a[1]), "r"(a[2]), "r"(a[3]), "r"(b[0]), "r"(b[1]));
}
__device__ __forceinline__ uint32_t hswap(uint32_t v) {
    uint32_t r;
    asm("prmt.b32 %0, %1, %1, 0x1032;" : "=r"(r) : "r"(v));
    return r;
}
__device__ __forceinline__ void splitpack2(float f0, float f1,
                                           uint32_t& w0, uint32_t& w1) {
    uint32_t h, l;
    asm("cvt.rn.bf16x2.f32 %0, %1, %2;" : "=r"(h) : "f"(f1), "f"(f0));
    float f0h = __uint_as_float(h << 16);
    float f1h = __uint_as_float(h & 0xffff0000u);
    asm("cvt.rn.bf16x2.f32 %0, %1, %2;" : "=r"(l) : "f"(f1 - f1h), "f"(f0 - f0h));
    asm("prmt.b32 %0, %1, %2, 0x5410;" : "=r"(w0) : "r"(h), "r"(l));
    asm("prmt.b32 %0, %1, %2, 0x7632;" : "=r"(w1) : "r"(h), "r"(l));
}

// ---------------- kernel 2: bucketed fused GEMM, pipelined HMMA ----------------
__global__ void __launch_bounds__(128, 4)
mma_kernel(const float* __restrict__ x,
           const float* __restrict__ W1,
           const float* __restrict__ W2,
           float* __restrict__ out) {
    extern __shared__ char smraw[];
    __shared__ int s_c[NHEAD];

    const int tid  = threadIdx.x;
    const int lane = tid & 31;
    const int warp = tid >> 5;

    // ---- read counts, publish, ticket-zero for next graph replay ----
    if (tid == 0) {
        s_c[0] = g_cnt[0]; s_c[1] = g_cnt[1];
        s_c[2] = g_cnt[2]; s_c[3] = g_cnt[3];
    }
    __syncthreads();
    if (tid == 0) {
        unsigned int old = atomicAdd(&g_done, 1u);
        if (old % gridDim.x == gridDim.x - 1) {
            g_cnt[0] = 0; g_cnt[1] = 0; g_cnt[2] = 0; g_cnt[3] = 0;
        }
    }

    // ---- resolve (head, tile) ----
    const int c0 = s_c[0], c1 = s_c[1], c2 = s_c[2], c3 = s_c[3];
    const int t0 = (c0 + TM - 1) >> 7, t1 = (c1 + TM - 1) >> 7,
              t2 = (c2 + TM - 1) >> 7, t3 = (c3 + TM - 1) >> 7;
    int b = blockIdx.x;
    int hd, cnt;
    if (b < t0)              { hd = 0; cnt = c0; }
    else if ((b -= t0) < t1) { hd = 1; cnt = c1; }
    else if ((b -= t1) < t2) { hd = 2; cnt = c2; }
    else if ((b -= t2) < t3) { hd = 3; cnt = c3; }
    else return;
    const int start = b << 7;

    const uint32_t raw  = smem_u32(smraw);
    const uint32_t base = (raw + 1023u) & ~1023u;
    char* smc = smraw + (base - raw);

    // ---- prologue: row indices, scaled W2, B tile ----
    {
        int rr = start + tid;
        if (rr >= cnt) rr = cnt - 1;
        *(int*)(smc + OFF_IDX + tid * 4) = g_idx[hd][rr];
    }
    {
        int j = tid >> 2, d = tid & 3;
        *(float*)(smc + OFF_W2 + tid * 4) =
            W2[(hd * HBLK + j) * DOUT + d] * 0.08838834764831845f;
    }
    {
        const int n  = tid & 31;
        const int k0 = tid >> 5;
        const uint32_t nc = (uint32_t)(n >> 3);
        const float* wp = W1 + hd * HBLK + n;
        #pragma unroll 4
        for (int i = 0; i < 64; ++i) {
            int k = k0 + 4 * i;
            float w = wp[k * DHID] * 0.0625f;       // fold 1/sqrt(256)
            __nv_bfloat16 hb = __float2bfloat16(w);
            float hf = __bfloat162float(hb);
            __nv_bfloat16 lb = __float2bfloat16(w - hf);
            uint32_t off = OFF_B + (uint32_t)(2 * k) * 64u +
                           (((uint32_t)nc ^ (uint32_t)(k & 3)) << 4) +
                           (uint32_t)(n & 7) * 2u;
            *(__nv_bfloat16*)(smc + off)      = hb;
            *(__nv_bfloat16*)(smc + off + 64) = lb;
        }
    }
    __syncthreads();

    // ---- gather lane constants: s3 = 16B slot (4 per row), rq = row-in-round ----
    const int s3 = lane & 3;
    const int rq = lane >> 2;                       // 0..7
    const uint32_t sts_sw = ((uint32_t)(s3 ^ ((lane >> 3) & 3))) << 4;
    uint32_t rofs[4];
    uint32_t rbyte[4];                              // row*64 for STS
    #pragma unroll
    for (int i = 0; i < 4; ++i) {
        int r = i * 32 + warp * 8 + rq;
        rofs[i]  = *(const uint32_t*)(smc + OFF_IDX + r * 4) * 1024u
                   + (uint32_t)(s3 * 16);
        rbyte[i] = (uint32_t)r * 64u + sts_sw;
    }
    const char* xB = (const char*)x;

    // ---- MMA lane constants ----
    const int g     = lane >> 3;
    const int l7    = lane & 7;
    const int ghalf = g >> 1;
    const int arow  = warp * 32 + (g & 1) * 8 + l7;
    const uint32_t aswz = (uint32_t)((l7 >> 1) & 3);
    const int klo   = (g & 1) * 8 + l7;
    const uint32_t abase = base + OFF_A0 + (uint32_t)arow * 64u;

    float acc[2][4][4];
    #pragma unroll
    for (int mt = 0; mt < 2; ++mt)
        #pragma unroll
        for (int nt = 0; nt < 4; ++nt)
            #pragma unroll
            for (int j = 0; j < 4; ++j) acc[mt][nt][j] = 0.f;

    // prologue: stage chunk 0
    float4 st[4];
    #pragma unroll
    for (int i = 0; i < 4; ++i) st[i] = *(const float4*)(xB + rofs[i]);

    #pragma unroll 1
    for (int ch = 0; ch < NCHUNK; ++ch) {
        const uint32_t bufo = (uint32_t)(ch & 1) * 8192u;

        // ---- convert + STS current chunk into buf ----
        #pragma unroll
        for (int i = 0; i < 4; ++i) {
            uint4 wv;
            splitpack2(st[i].x, st[i].y, wv.x, wv.y);
            splitpack2(st[i].z, st[i].w, wv.z, wv.w);
            *(uint4*)(smc + OFF_A0 + bufo + rbyte[i]) = wv;
        }
        __syncthreads();

        // ---- prefetch next chunk (LDG overlaps the MMA below) ----
        float4 nx[4];
        if (ch + 1 < NCHUNK) {
            uint32_t add = (uint32_t)(ch + 1) * 64u;
            #pragma unroll
            for (int i = 0; i < 4; ++i)
                nx[i] = *(const float4*)(xB + rofs[i] + add);
        }

        // ---- MMA on buf: 2 k-steps (cat-K 16 each) ----
        #pragma unroll
        for (int ksl = 0; ksl < 2; ++ksl) {
            uint32_t afr[2][4], asw[2][4], bfr[2][4];
            const uint32_t cc = (uint32_t)(2 * ksl + ghalf);
            #pragma unroll
            for (int mt = 0; mt < 2; ++mt)
                ldm_x4(afr[mt], abase + bufo + (uint32_t)mt * 1024u +
                                ((cc ^ aswz) << 4));
            {
                int row = ch * 32 + ksl * 16 + klo;
                uint32_t bsw = (uint32_t)((row >> 1) & 3);
                #pragma unroll
                for (int np = 0; np < 2; ++np) {
                    uint32_t nc2 = (uint32_t)(np * 2 + ghalf);
                    ldm_x4_t(bfr[np], base + OFF_B + (uint32_t)row * 64u +
                                      ((nc2 ^ bsw) << 4));
                }
            }
            #pragma unroll
            for (int mt = 0; mt < 2; ++mt)
                #pragma unroll
                for (int j = 0; j < 4; ++j) asw[mt][j] = hswap(afr[mt][j]);
            #pragma unroll
            for (int mt = 0; mt < 2; ++mt)
                #pragma unroll
                for (int np = 0; np < 2; ++np) {
                    mma_bf16(acc[mt][np * 2 + 0], afr[mt], bfr[np] + 0);
                    mma_bf16(acc[mt][np * 2 + 1], afr[mt], bfr[np] + 2);
                    mma_bf16(acc[mt][np * 2 + 0], asw[mt], bfr[np] + 0);
                    mma_bf16(acc[mt][np * 2 + 1], asw[mt], bfr[np] + 2);
                }
        }

        #pragma unroll
        for (int i = 0; i < 4; ++i) st[i] = nx[i];
    }

    // ---- epilogue: silu + W2, quad reduction, scattered store ----
    const int q  = lane & 3;
    const int r0 = lane >> 2;

    float4 osum[2][2];
    #pragma unroll
    for (int mt = 0; mt < 2; ++mt)
        #pragma unroll
        for (int hh = 0; hh < 2; ++hh)
            osum[mt][hh] = make_float4(0.f, 0.f, 0.f, 0.f);

    #pragma unroll
    for (int nt = 0; nt < 4; ++nt) {
        float4 wcj[2];
        #pragma unroll
        for (int j = 0; j < 2; ++j)
            wcj[j] = *(const float4*)(smc + OFF_W2 + (nt * 8 + q * 2 + j) * 16);
        #pragma unroll
        for (int mt = 0; mt < 2; ++mt)
            #pragma unroll
            for (int idx = 0; idx < 4; ++idx) {
                int hh = idx >> 1, j = idx & 1;
                float hv = acc[mt][nt][idx];
                float sv = hv / (1.f + __expf(-hv));
                osum[mt][hh].x += sv * wcj[j].x;
                osum[mt][hh].y += sv * wcj[j].y;
                osum[mt][hh].z += sv * wcj[j].z;
                osum[mt][hh].w += sv * wcj[j].w;
            }
    }

    #pragma unroll
    for (int mbit = 1; mbit <= 2; mbit <<= 1)
        #pragma unroll
        for (int mt = 0; mt < 2; ++mt)
            #pragma unroll
            for (int hh = 0; hh < 2; ++hh) {
                osum[mt][hh].x += __shfl_xor_sync(0xffffffffu, osum[mt][hh].x, mbit);
                osum[mt][hh].y += __shfl_xor_sync(0xffffffffu, osum[mt][hh].y, mbit);
                osum[mt][hh].z += __shfl_xor_sync(0xffffffffu, osum[mt][hh].z, mbit);
                osum[mt][hh].w += __shfl_xor_sync(0xffffffffu, osum[mt][hh].w, mbit);
            }

    if (q == 0) {
        #pragma unroll
        for (int mt = 0; mt < 2; ++mt)
            #pragma unroll
            for (int hh = 0; hh < 2; ++hh) {
                int rl = warp * 32 + mt * 16 + hh * 8 + r0;
                if (start + rl < cnt) {
                    int ridx = *(const int*)(smc + OFF_IDX + rl * 4);
                    *(float4*)(out + (size_t)ridx * DOUT) = osum[mt][hh];
                }
            }
    }
}

// ---------------- launch ----------------
extern "C" void kernel_launch(void* const* d_in, const int* in_sizes, int n_in,
                              void* d_out, int out_size) {
    const float* x     = (const float*)d_in[0];
    const float* W1    = (const float*)d_in[1];
    const float* W2    = (const float*)d_in[2];
    const int*   heads = (const int*)d_in[3];
    int n = in_sizes[3];

    static int attr_done = 0;
    if (!attr_done) {
        cudaFuncSetAttribute(mma_kernel,
                             cudaFuncAttributeMaxDynamicSharedMemorySize, SMEM_REQ);
        attr_done = 1;
    }

    scatter_kernel<<<(n + 255) / 256, 256>>>(heads, n);

    int nt = (n + TM - 1) / TM + (NHEAD - 1);
    mma_kernel<<<nt, 128, SMEM_REQ>>>(x, W1, W2, (float*)d_out);
}